// round 5
// baseline (speedup 1.0000x reference)
#include <cuda_runtime.h>
#include <cstdint>

#define NN 8192
#define DD 64
#define EE 16384
#define NEGV -1e10f
#define TINYF 1.17549435e-38f

#define NB 128
#define NT 256
#define TILE_J 128
#define TILE_STRIDE 68          // floats; 272B rows, LDS.128-friendly
#define NCHUNK (NN / TILE_J)    // 64
#define CAND_TILE 32

// ---------------- scratch ----------------
__device__ float g_queries[NN * DD];
__device__ float g_qn[NN];
__device__ float g_hn[NN];
__device__ int   g_gens0[NN];
__device__ int   g_glist[NN];
__device__ int   g_flag[NN];
__device__ unsigned long long g_best[NN];
__device__ int   g_newsend[NN];
__device__ int   g_newrec[NN];
__device__ int   g_ngens;
__device__ int   g_eactive;
__device__ int   g_ncand;

// grid barrier state (generation-based; survives graph replays)
__device__ int g_bar_count = 0;
__device__ volatile int g_bar_gen = 0;

__device__ __forceinline__ void grid_bar() {
  __syncthreads();
  if (threadIdx.x == 0) {
    int gen = g_bar_gen;
    __threadfence();                       // order my writes + CCTL.IVALL
    if (atomicAdd(&g_bar_count, 1) == NB - 1) {
      g_bar_count = 0;
      __threadfence();
      g_bar_gen = gen + 1;                 // release
    } else {
      while (g_bar_gen == gen) { }
    }
    __threadfence();                       // invalidate L1 before next phase reads
  }
  __syncthreads();
}

// ---------------- threefry2x32 (JAX-exact) ----------------
__host__ __device__ __forceinline__ void threefry2x32(uint32_t k0, uint32_t k1,
                                                      uint32_t x0, uint32_t x1,
                                                      uint32_t* o0, uint32_t* o1) {
  uint32_t ks2 = k0 ^ k1 ^ 0x1BD11BDAu;
#define ROTL32(v, r) (((v) << (r)) | ((v) >> (32 - (r))))
#define TFRND(r) { x0 += x1; x1 = ROTL32(x1, r); x1 ^= x0; }
  x0 += k0; x1 += k1;
  TFRND(13) TFRND(15) TFRND(26) TFRND(6)
  x0 += k1; x1 += ks2 + 1u;
  TFRND(17) TFRND(29) TFRND(16) TFRND(24)
  x0 += ks2; x1 += k0 + 2u;
  TFRND(13) TFRND(15) TFRND(26) TFRND(6)
  x0 += k0; x1 += k1 + 3u;
  TFRND(17) TFRND(29) TFRND(16) TFRND(24)
  x0 += k1; x1 += ks2 + 4u;
  TFRND(13) TFRND(15) TFRND(26) TFRND(6)
  x0 += ks2; x1 += k0 + 5u;
  *o0 = x0; *o1 = x1;
#undef TFRND
#undef ROTL32
}

__device__ __forceinline__ uint32_t random_bits32(uint32_t k0, uint32_t k1,
                                                  unsigned long long idx) {
  uint32_t o0, o1;
  threefry2x32(k0, k1, (uint32_t)(idx >> 32), (uint32_t)idx, &o0, &o1);
  return o0 ^ o1;
}

__device__ __forceinline__ float u01_from_bits(uint32_t bits) {
  return __uint_as_float((bits >> 9) | 0x3f800000u) - 1.0f;
}

// XLA ErfInv (Giles)
__device__ __forceinline__ float xla_erfinv(float x) {
  float w = -log1pf(-x * x);
  float p;
  if (w < 5.f) {
    w -= 2.5f;
    p = 2.81022636e-08f;
    p = fmaf(p, w, 3.43273939e-07f);
    p = fmaf(p, w, -3.5233877e-06f);
    p = fmaf(p, w, -4.39150654e-06f);
    p = fmaf(p, w, 0.00021858087f);
    p = fmaf(p, w, -0.00125372503f);
    p = fmaf(p, w, -0.00417768164f);
    p = fmaf(p, w, 0.246640727f);
    p = fmaf(p, w, 1.50140941f);
  } else {
    w = sqrtf(w) - 3.f;
    p = -0.000200214257f;
    p = fmaf(p, w, 0.000100950558f);
    p = fmaf(p, w, 0.00134934322f);
    p = fmaf(p, w, -0.00367342844f);
    p = fmaf(p, w, 0.00573950773f);
    p = fmaf(p, w, -0.0076224613f);
    p = fmaf(p, w, 0.00943887047f);
    p = fmaf(p, w, 1.00167406f);
    p = fmaf(p, w, 2.83297682f);
  }
  return p * x;
}

// monotone (value, smallest-j-wins) encoding for 64-bit atomicMax
__device__ __forceinline__ unsigned long long enc_key(float v, int j) {
  uint32_t u = __float_as_uint(v);
  u = (u & 0x80000000u) ? ~u : (u | 0x80000000u);
  return ((unsigned long long)u << 32) | (unsigned long long)(0xFFFFFFFFu - (uint32_t)j);
}

__device__ __forceinline__ int warp_incl_scan(int v, int lane) {
#pragma unroll
  for (int d = 1; d < 32; d <<= 1) {
    int o = __shfl_up_sync(0xffffffffu, v, d);
    if (lane >= d) v += o;
  }
  return v;
}

// =================== THE fused persistent kernel ===================
__global__ void __launch_bounds__(NT, 1)
k_fused(const float* __restrict__ nodes, const float* __restrict__ edges,
        const int* __restrict__ receivers, const int* __restrict__ senders,
        const float* __restrict__ active_nodes, const float* __restrict__ active_edges,
        const float* __restrict__ Wq, const float* __restrict__ bq,
        const float* __restrict__ Wp, const float* __restrict__ bp,
        float* __restrict__ out, int out_size,
        uint32_t kp0, uint32_t kp1, uint32_t ke0, uint32_t ke1,
        uint32_t ks0, uint32_t ks1) {
  __shared__ __align__(16) float sh[TILE_J * TILE_STRIDE];   // 34816 B (aliased per phase)
  __shared__ __align__(16) float qsh[CAND_TILE * DD];        // 8192 B  (aliased per phase)
  __shared__ float s_qn[CAND_TILE];
  __shared__ int   s_ii[CAND_TILE];
  __shared__ int   swA[32];
  __shared__ int   swB[33];
  __shared__ float swF[8];

  const int tid = threadIdx.x;
  const int lane = tid & 31;
  const int wid = tid >> 5;          // 0..7
  const int bid = blockIdx.x;

  // ---------------- Phase 0: prep (queries, norms, Bernoulli) ----------------
  {
    float* sWq = sh;                 // 4096 floats
    float* sbq = qsh;                // 64
    float* sWp = qsh + 64;           // 64
    {
      const float4* w4 = reinterpret_cast<const float4*>(Wq);
      float4* s4 = reinterpret_cast<float4*>(sWq);
#pragma unroll
      for (int r = 0; r < 4; r++) s4[tid + (r << 8)] = w4[tid + (r << 8)];
      if (tid < DD) { sbq[tid] = bq[tid]; sWp[tid] = Wp[tid]; }
    }
    __syncthreads();
    const float bp0 = bp[0];
#pragma unroll
    for (int r = 0; r < 8; r++) {
      const int i = (bid << 6) + (wid << 3) + r;
      float2 n2 = reinterpret_cast<const float2*>(nodes + i * DD)[lane];
      float2 b2 = reinterpret_cast<const float2*>(sbq)[lane];
      float q0 = b2.x, q1 = b2.y;
#pragma unroll
      for (int k = 0; k < DD; k++) {
        float nk = __shfl_sync(0xffffffffu, (k & 1) ? n2.y : n2.x, k >> 1);
        float2 w = reinterpret_cast<const float2*>(sWq + k * DD)[lane];
        q0 = fmaf(nk, w.x, q0);
        q1 = fmaf(nk, w.y, q1);
      }
      reinterpret_cast<float2*>(g_queries + i * DD)[lane] = make_float2(q0, q1);
      float2 wp2 = reinterpret_cast<const float2*>(sWp)[lane];
      float rq = q0 * q0 + q1 * q1;
      float rh = n2.x * n2.x + n2.y * n2.y;
      float rp = n2.x * wp2.x + n2.y * wp2.y;
#pragma unroll
      for (int d = 16; d > 0; d >>= 1) {
        rq += __shfl_xor_sync(0xffffffffu, rq, d);
        rh += __shfl_xor_sync(0xffffffffu, rh, d);
        rp += __shfl_xor_sync(0xffffffffu, rp, d);
      }
      if (lane == 0) {
        g_qn[i] = rq;
        g_hn[i] = rh;
        float z = rp + bp0;
        float prob = 0.5f * tanhf(0.5f * z) + 0.5f;   // XLA logistic
        uint32_t bits = random_bits32(kp0, kp1, (unsigned long long)i);
        float u = u01_from_bits(bits);
        g_gens0[i] = (u < prob * active_nodes[i]) ? 1 : 0;
        g_best[i] = 0ull;
      }
    }
  }
  grid_bar();

  // ---------------- Phase 1: listgen (block 0 only) ----------------
  if (bid == 0) {
    // e_active sum
    const float4* ae4 = reinterpret_cast<const float4*>(active_edges);
    float s = 0.f;
#pragma unroll
    for (int r = 0; r < 16; r++) {
      float4 v = ae4[tid + (r << 8)];
      s += v.x + v.y + v.z + v.w;
    }
#pragma unroll
    for (int d = 16; d > 0; d >>= 1) s += __shfl_xor_sync(0xffffffffu, s, d);
    if (lane == 0) swF[wid] = s;

    // generator bitmask: 32 flags per thread
    uint32_t fm = 0;
    const int4* g4 = reinterpret_cast<const int4*>(g_gens0 + tid * 32);
#pragma unroll
    for (int r = 0; r < 8; r++) {
      int4 v = g4[r];
      fm |= (uint32_t)v.x << (r * 4);
      fm |= (uint32_t)v.y << (r * 4 + 1);
      fm |= (uint32_t)v.z << (r * 4 + 2);
      fm |= (uint32_t)v.w << (r * 4 + 3);
    }
    int cnt = __popc(fm);
    int incl = warp_incl_scan(cnt, lane);
    if (lane == 31) swA[wid] = incl;
    __syncthreads();
    if (tid == 0) {
      swB[0] = 0;
#pragma unroll
      for (int w = 0; w < 8; w++) swB[w + 1] = swB[w] + swA[w];
      g_ncand = swB[8];
      float t = 0.f;
#pragma unroll
      for (int w = 0; w < 8; w++) t += swF[w];
      g_eactive = (int)t;
    }
    __syncthreads();
    int off = swB[wid] + incl - cnt;
    // NOTE: bit r of fm corresponds to element tid*32 + (r%4)*... careful mapping below
    // mapping above: bit index (r*4 + c) corresponds to element tid*32 + r*4 + c  -> linear
#pragma unroll
    for (int r = 0; r < 32; r++) {
      if ((fm >> r) & 1u) {
        g_glist[off] = tid * 32 + r;
        g_flag[off] = 1;
        off++;
      }
    }
  }
  grid_bar();

  // ---------------- Phase 2: select (tiled scoring + gumbel argmax) ----------------
  {
    const int jj = tid & 127;
    const int grp2 = tid >> 7;               // 0 or 1
    const int ncand = g_ncand;
    const int ng = (ncand + CAND_TILE - 1) / CAND_TILE;
    const int total = NCHUNK * ng;
    for (int w = bid; w < total; w += NB) {
      const int chunk = w / ng;
      const int grp = w - chunk * ng;
      const int c0 = grp * CAND_TILE;
      const int jbase = chunk << 7;
      {
        const float4* src = reinterpret_cast<const float4*>(nodes + (jbase << 6));
#pragma unroll
        for (int s = 0; s < 8; s++) {
          int idx4 = (s << 8) + tid;
          int row = idx4 >> 4, col4 = idx4 & 15;
          reinterpret_cast<float4*>(sh + row * TILE_STRIDE)[col4] = src[idx4];
        }
      }
      if (tid < CAND_TILE) {
        int idx = c0 + tid;
        int i = (idx < ncand) ? g_glist[idx] : 0;
        s_ii[tid] = i;
        s_qn[tid] = g_qn[i];
      }
#pragma unroll
      for (int s = 0; s < 2; s++) {
        int t4 = (s << 8) + tid;
        int c = t4 >> 4, k4 = t4 & 15;
        int idx = c0 + c;
        float4 qv = (idx < ncand)
            ? reinterpret_cast<const float4*>(g_queries + g_glist[idx] * DD)[k4]
            : make_float4(0.f, 0.f, 0.f, 0.f);
        reinterpret_cast<float4*>(qsh + c * DD)[k4] = qv;
      }
      __syncthreads();
      const int j = jbase + jj;
      const float hn = g_hn[j];
      const float act = active_nodes[j];
      const float4* rowf4 = reinterpret_cast<const float4*>(sh + jj * TILE_STRIDE);
      const int clim = (ncand - c0 < CAND_TILE) ? (ncand - c0) : CAND_TILE;
      const int cbeg = grp2 << 4;
      const int cend = (cbeg + 16 < clim) ? cbeg + 16 : clim;
      for (int c = cbeg; c < cend; c++) {
        const int i = s_ii[c];
        const float4* qf4 = reinterpret_cast<const float4*>(qsh + c * DD);
        float ax = 0.f, ay = 0.f, az = 0.f, aw = 0.f;
#pragma unroll
        for (int kk = 0; kk < 16; kk++) {
          float4 r = rowf4[kk];
          float4 q = qf4[kk];
          ax = fmaf(q.x, r.x, ax);
          ay = fmaf(q.y, r.y, ay);
          az = fmaf(q.z, r.z, az);
          aw = fmaf(q.w, r.w, aw);
        }
        float num = (ax + az) + (ay + aw);
        float sc = num / (sqrtf(s_qn[c] * hn) + 1e-8f);
        sc = fminf(fmaxf(sc, -10000.f), 10000.f);
        if (act <= 0.f) sc = NEGV;
        if (j == i) sc = NEGV;
        unsigned long long lin = (unsigned long long)i * NN + (unsigned long long)j;
        uint32_t bits = random_bits32(ks0, ks1, lin);
        float u = fmaxf(TINYF, u01_from_bits(bits) + TINYF);
        float g = -logf(-logf(u));
        unsigned long long key = enc_key(sc + g, j);
#pragma unroll
        for (int d = 16; d > 0; d >>= 1) {
          unsigned long long o = __shfl_xor_sync(0xffffffffu, key, d);
          if (o > key) key = o;
        }
        if (lane == 0) atomicMax(&g_best[i], key);
      }
      __syncthreads();
    }
  }
  grid_bar();

  // ---------------- Phase 3: exist check (blocks 0..63, 1 edge/thread) ----------------
  if (bid < EE / NT) {
    unsigned long long* keys = reinterpret_cast<unsigned long long*>(sh);  // cap 4352
    const int ncand = g_ncand;
    const int e = (bid << 8) + tid;
    const unsigned long long ekey =
        ((unsigned long long)(uint32_t)senders[e] << 32) | (uint32_t)receivers[e];
    for (int base = 0; base < ncand; base += 4096) {
      int m = ncand - base;
      if (m > 4096) m = 4096;
      for (int t = tid; t < m; t += NT) {
        int i = g_glist[base + t];
        unsigned long long b = g_best[i];
        uint32_t sel = 0xFFFFFFFFu - (uint32_t)(b & 0xFFFFFFFFull);
        keys[t] = ((unsigned long long)(uint32_t)i << 32) | sel;
      }
      __syncthreads();
      for (int k = 0; k < m; k++) {
        if (ekey == keys[k]) g_flag[base + k] = 0;
      }
      __syncthreads();
    }
  }
  grid_bar();

  // ---------------- Phase 4: compact (block 0 only) ----------------
  if (bid == 0) {
    const int ncand = g_ncand;
    uint32_t fm = 0;
#pragma unroll
    for (int r = 0; r < 32; r++) {
      int c = tid * 32 + r;
      int f = (c < ncand) ? g_flag[c] : 0;
      fm |= (uint32_t)f << r;
    }
    int cnt = __popc(fm);
    int incl = warp_incl_scan(cnt, lane);
    if (lane == 31) swA[wid] = incl;
    __syncthreads();
    if (tid == 0) {
      swB[0] = 0;
#pragma unroll
      for (int w = 0; w < 8; w++) swB[w + 1] = swB[w] + swA[w];
      int total = swB[8];
      int allowed = EE - g_eactive - 1;
      int n = total < 0 ? 0 : total;
      if (n > allowed) n = allowed;
      g_ngens = n;
    }
    __syncthreads();
    int off = swB[wid] + incl - cnt;
#pragma unroll
    for (int r = 0; r < 32; r++) {
      if ((fm >> r) & 1u) {
        int c = tid * 32 + r;
        int i = g_glist[c];
        unsigned long long b = g_best[i];
        g_newsend[off] = i;
        g_newrec[off] = (int)(0xFFFFFFFFu - (uint32_t)(b & 0xFFFFFFFFull));
        off++;
      }
    }
  }
  grid_bar();

  // ---------------- Phase 5: output writer ----------------
  {
    const int ngen = g_ngens;
    const int ea = g_eactive;
    const int T1 = EE * DD;
    const int n4 = out_size >> 2;
    float4* out4 = reinterpret_cast<float4*>(out);
    const int gtid = bid * NT + tid;
    for (int idx4 = gtid; idx4 < n4; idx4 += NB * NT) {
      int base = idx4 << 2;
      float4 v;
      if (base < T1) {
        v = reinterpret_cast<const float4*>(edges)[idx4];
        int e = base >> 6;
        if (e >= ea && e < ea + ngen) {
          float* vp = reinterpret_cast<float*>(&v);
#pragma unroll
          for (int cmp = 0; cmp < 4; cmp++) {
            uint32_t bits = random_bits32(ke0, ke1, (unsigned long long)(base + cmp));
            float u01 = u01_from_bits(bits);
            const float lo = -0.99999994f;
            float uu = fmaxf(lo, fmaf(u01, 2.0f, lo));
            vp[cmp] += 1.41421356f * xla_erfinv(uu);
          }
        }
      } else if (base < T1 + EE) {
        float* vp = reinterpret_cast<float*>(&v);
#pragma unroll
        for (int cmp = 0; cmp < 4; cmp++) {
          int j = base + cmp - T1;
          float x;
          if (j < ea)             x = (float)senders[j];
          else if (j < ea + ngen) x = (float)g_newsend[j - ea];
          else                    x = (float)(NN - 1);
          vp[cmp] = x;
        }
      } else if (base < T1 + 2 * EE) {
        float* vp = reinterpret_cast<float*>(&v);
#pragma unroll
        for (int cmp = 0; cmp < 4; cmp++) {
          int j = base + cmp - T1 - EE;
          float x;
          if (j < ea)             x = (float)receivers[j];
          else if (j < ea + ngen) x = (float)g_newrec[j - ea];
          else                    x = (float)(NN - 1);
          vp[cmp] = x;
        }
      } else {
        float* vp = reinterpret_cast<float*>(&v);
#pragma unroll
        for (int cmp = 0; cmp < 4; cmp++) {
          int j = base + cmp - T1 - 2 * EE;
          vp[cmp] = (j < ea + ngen) ? 1.0f : 0.0f;
        }
      }
      out4[idx4] = v;
    }
    // scalar tail (out_size not divisible by 4 — not expected)
    for (int idx = (n4 << 2) + gtid; idx < out_size; idx += NB * NT) {
      float x = 0.f;
      if (idx < T1) {
        x = edges[idx];
        int e = idx >> 6;
        if (e >= ea && e < ea + ngen) {
          uint32_t bits = random_bits32(ke0, ke1, (unsigned long long)idx);
          float u01 = u01_from_bits(bits);
          const float lo = -0.99999994f;
          float u = fmaxf(lo, fmaf(u01, 2.0f, lo));
          x += 1.41421356f * xla_erfinv(u);
        }
      } else if (idx < T1 + EE) {
        int j = idx - T1;
        if (j < ea)             x = (float)senders[j];
        else if (j < ea + ngen) x = (float)g_newsend[j - ea];
        else                    x = (float)(NN - 1);
      } else if (idx < T1 + 2 * EE) {
        int j = idx - T1 - EE;
        if (j < ea)             x = (float)receivers[j];
        else if (j < ea + ngen) x = (float)g_newrec[j - ea];
        else                    x = (float)(NN - 1);
      } else if (idx < T1 + 3 * EE) {
        int j = idx - T1 - 2 * EE;
        x = (j < ea + ngen) ? 1.0f : 0.0f;
      }
      out[idx] = x;
    }
  }
}

// ---------------- host ----------------
extern "C" void kernel_launch(void* const* d_in, const int* in_sizes, int n_in,
                              void* d_out, int out_size) {
  const float* nodes        = (const float*)d_in[0];
  const float* edges        = (const float*)d_in[1];
  const int*   receivers    = (const int*)d_in[2];
  const int*   senders      = (const int*)d_in[3];
  const float* active_nodes = (const float*)d_in[4];
  const float* active_edges = (const float*)d_in[5];
  const float* Wq           = (const float*)d_in[6];
  const float* bq           = (const float*)d_in[7];
  const float* Wp           = (const float*)d_in[8];
  const float* bp           = (const float*)d_in[9];
  (void)in_sizes; (void)n_in;

  const uint32_t K0 = 0u, K1 = 42u;
  uint32_t kp0, kp1, ke0, ke1, ks0, ks1;
  threefry2x32(K0, K1, 0u, 0u, &kp0, &kp1);  // key_prob
  threefry2x32(K0, K1, 0u, 1u, &ke0, &ke1);  // key_edges
  threefry2x32(K0, K1, 0u, 2u, &ks0, &ks1);  // key_samp

  k_fused<<<NB, NT>>>(nodes, edges, receivers, senders, active_nodes, active_edges,
                      Wq, bq, Wp, bp, (float*)d_out, out_size,
                      kp0, kp1, ke0, ke1, ks0, ks1);
}